// round 9
// baseline (speedup 1.0000x reference)
#include <cuda_runtime.h>
#include <cuda_bf16.h>
#include <math.h>

// Problem constants
#define BB   2
#define SS   2048
#define DD   2048
#define HQ   16
#define HKV  4
#define HD   128
#define GQ   (HQ / HKV)          // 4

// ---------------------------------------------------------------------------
// Scratch (device globals; no dynamic allocation allowed)
// ---------------------------------------------------------------------------
__device__ float g_Q[(size_t)BB * SS * HQ * HD];
__device__ float g_K[(size_t)BB * SS * HKV * HD];
__device__ float g_V[(size_t)BB * SS * HKV * HD];
__device__ float g_O[(size_t)BB * SS * HQ * HD];

// ---------------------------------------------------------------------------
// TF32 split-precision GEMM v2: cp.async double-buffered, consumer-side split.
// C[M,N] = A[M,K] @ B[K,N], row-major. 3-pass tf32 (hi*hi + hi*lo + lo*hi).
// 128x128 block tile, BK=16, 512 threads (16 warps, 4x4), warp tile 32x32.
// ---------------------------------------------------------------------------
#define GBM 128
#define GBN 128
#define GBK 16
#define ASTR 20    // A smem row stride (floats): 20*lg+lk -> conflict-free
#define BSTR 136   // B smem row stride (floats): 8*lk+lg  -> conflict-free

__device__ __forceinline__ unsigned f2tf32(float f) {
    unsigned u;
    asm("cvt.rna.tf32.f32 %0, %1;" : "=r"(u) : "f"(f));
    return u;
}

__device__ __forceinline__ void mma_tf32(float* c, const unsigned* a, const unsigned* b) {
    asm volatile(
        "mma.sync.aligned.m16n8k8.row.col.f32.tf32.tf32.f32 "
        "{%0,%1,%2,%3}, {%4,%5,%6,%7}, {%8,%9}, {%0,%1,%2,%3};\n"
        : "+f"(c[0]), "+f"(c[1]), "+f"(c[2]), "+f"(c[3])
        : "r"(a[0]), "r"(a[1]), "r"(a[2]), "r"(a[3]), "r"(b[0]), "r"(b[1]));
}

__device__ __forceinline__ void cp16(float* dst_smem, const float* src_gmem) {
    unsigned d = (unsigned)__cvta_generic_to_shared(dst_smem);
    asm volatile("cp.async.ca.shared.global [%0], [%1], 16;\n" :: "r"(d), "l"(src_gmem));
}
__device__ __forceinline__ void cp_commit() {
    asm volatile("cp.async.commit_group;\n" ::: "memory");
}
template <int N>
__device__ __forceinline__ void cp_wait() {
    asm volatile("cp.async.wait_group %0;\n" :: "n"(N) : "memory");
}

// Shared device body: computes one 128x128 tile of C = A @ B (512 threads).
__device__ __forceinline__ void gemm_tile_body(
    const float* __restrict__ A, const float* __restrict__ B,
    float* __restrict__ C, int K, int Nout, int block_m, int block_n)
{
    __shared__ float As[2][GBM * ASTR];   // [m][k] raw fp32, stride 20
    __shared__ float Bs[2][GBK * BSTR];   // [k][n] raw fp32, stride 136

    const int t    = threadIdx.x;
    const int lane = t & 31;
    const int wid  = t >> 5;              // 0..15
    const int warp_m = (wid & 3) * 32;
    const int warp_n = (wid >> 2) * 32;

    const int lk = lane & 3;              // frag k sub-index
    const int lg = lane >> 2;             // frag group (0..7)

    // cp.async chunk mapping (one A chunk + one B chunk per thread)
    const int a_row = t >> 2;             // 0..127
    const int a_c   = (t & 3) << 2;       // float col 0,4,8,12
    const int b_row = t >> 5;             // 0..15 (k)
    const int b_c   = (t & 31) << 2;      // float col 0..124

    float acc[2][4][4];
    #pragma unroll
    for (int mt = 0; mt < 2; mt++)
        #pragma unroll
        for (int nt = 0; nt < 4; nt++)
            #pragma unroll
            for (int i = 0; i < 4; i++) acc[mt][nt][i] = 0.0f;

    const int NT = K / GBK;

    // prologue: stage 0
    cp16(&As[0][a_row * ASTR + a_c], A + (size_t)(block_m + a_row) * K + a_c);
    cp16(&Bs[0][b_row * BSTR + b_c], B + (size_t)b_row * Nout + block_n + b_c);
    cp_commit();

    for (int i = 0; i < NT; i++) {
        if (i + 1 < NT) {
            const int s = (i + 1) & 1;
            const int k0 = (i + 1) * GBK;
            cp16(&As[s][a_row * ASTR + a_c], A + (size_t)(block_m + a_row) * K + k0 + a_c);
            cp16(&Bs[s][b_row * BSTR + b_c], B + (size_t)(k0 + b_row) * Nout + block_n + b_c);
            cp_commit();
            cp_wait<1>();
        } else {
            cp_wait<0>();
        }
        __syncthreads();

        const int s = i & 1;
        const float* as = As[s];
        const float* bs = Bs[s];

        #pragma unroll
        for (int ks = 0; ks < GBK; ks += 8) {
            // A frags: raw -> hi/lo in registers (layout identical to verified R7 kernel)
            unsigned ah[2][4], al[2][4];
            #pragma unroll
            for (int mt = 0; mt < 2; mt++) {
                const int m0 = warp_m + mt * 16 + lg;
                float r[4];
                r[0] = as[m0 * ASTR + ks + lk];           // (k=ks+lk,   m0)
                r[1] = as[(m0 + 8) * ASTR + ks + lk];     // (k=ks+lk,   m0+8)
                r[2] = as[m0 * ASTR + ks + lk + 4];       // (k=ks+lk+4, m0)
                r[3] = as[(m0 + 8) * ASTR + ks + lk + 4]; // (k=ks+lk+4, m0+8)
                #pragma unroll
                for (int j = 0; j < 4; j++) {
                    unsigned hi = f2tf32(r[j]);
                    ah[mt][j] = hi;
                    al[mt][j] = f2tf32(r[j] - __uint_as_float(hi));
                }
            }
            // B frags
            unsigned bh[4][2], bl[4][2];
            #pragma unroll
            for (int nt = 0; nt < 4; nt++) {
                const int n0 = warp_n + nt * 8 + lg;
                float s0 = bs[(ks + lk) * BSTR + n0];
                float s1 = bs[(ks + lk + 4) * BSTR + n0];
                unsigned h0 = f2tf32(s0), h1 = f2tf32(s1);
                bh[nt][0] = h0; bh[nt][1] = h1;
                bl[nt][0] = f2tf32(s0 - __uint_as_float(h0));
                bl[nt][1] = f2tf32(s1 - __uint_as_float(h1));
            }

            // pass 1: Ahi * Blo
            #pragma unroll
            for (int nt = 0; nt < 4; nt++)
                #pragma unroll
                for (int mt = 0; mt < 2; mt++)
                    mma_tf32(acc[mt][nt], ah[mt], bl[nt]);
            // pass 2: Ahi * Bhi
            #pragma unroll
            for (int nt = 0; nt < 4; nt++)
                #pragma unroll
                for (int mt = 0; mt < 2; mt++)
                    mma_tf32(acc[mt][nt], ah[mt], bh[nt]);
            // pass 3: Alo * Bhi
            #pragma unroll
            for (int nt = 0; nt < 4; nt++)
                #pragma unroll
                for (int mt = 0; mt < 2; mt++)
                    mma_tf32(acc[mt][nt], al[mt], bh[nt]);
        }
        __syncthreads();   // protect stage before it is overwritten next iter
    }

    // epilogue (layout identical to verified R7 kernel)
    #pragma unroll
    for (int mt = 0; mt < 2; mt++) {
        #pragma unroll
        for (int nt = 0; nt < 4; nt++) {
            int r0 = block_m + warp_m + mt * 16 + lg;
            int c0 = block_n + warp_n + nt * 8 + lk * 2;
            *(float2*)(C + (size_t)r0 * Nout + c0)       = make_float2(acc[mt][nt][0], acc[mt][nt][1]);
            *(float2*)(C + (size_t)(r0 + 8) * Nout + c0) = make_float2(acc[mt][nt][2], acc[mt][nt][3]);
        }
    }
}

// Plain GEMM (used for the output projection)
__global__ __launch_bounds__(512) void gemm_tf32_kernel(
    const float* __restrict__ A, const float* __restrict__ B,
    float* __restrict__ C, int M, int N, int K)
{
    gemm_tile_body(A, B, C, K, N, blockIdx.y * GBM, blockIdx.x * GBN);
}

// Fused QKV projection: one launch, N-tiles routed to (Wq,gQ)/(Wk,gK)/(Wv,gV).
// grid.x = 24 N-tiles: [0,16) -> Q (N=2048), [16,20) -> K (N=512), [20,24) -> V.
__global__ __launch_bounds__(512) void gemm_qkv_kernel(
    const float* __restrict__ x,
    const float* __restrict__ Wq, const float* __restrict__ Wk,
    const float* __restrict__ Wv,
    float* __restrict__ Qo, float* __restrict__ Ko, float* __restrict__ Vo)
{
    const int nt = blockIdx.x;
    const float* Bp;
    float* Cp;
    int Nout, tile;
    if (nt < 16)      { Bp = Wq; Cp = Qo; Nout = HQ * HD;  tile = nt; }
    else if (nt < 20) { Bp = Wk; Cp = Ko; Nout = HKV * HD; tile = nt - 16; }
    else              { Bp = Wv; Cp = Vo; Nout = HKV * HD; tile = nt - 20; }
    gemm_tile_body(x, Bp, Cp, DD, Nout, blockIdx.y * GBM, tile * GBN);
}

// ---------------------------------------------------------------------------
// Fused RMSNorm + RoPE (in place), one block per (b*S+s, head) row of 128
// ---------------------------------------------------------------------------
__global__ __launch_bounds__(128) void norm_rope_kernel(
    float* __restrict__ X, const float* __restrict__ w,
    const float* __restrict__ cosT, const float* __restrict__ sinT, int H)
{
    __shared__ float sm[HD];
    __shared__ float red[4];

    const int idx = blockIdx.x;
    const int h   = idx % H;
    const int row = idx / H;       // b*S + s
    const int s   = row % SS;
    float* p = X + (size_t)row * (H * HD) + h * HD;

    const int d = threadIdx.x;
    float v  = p[d];
    float ss = v * v;
    #pragma unroll
    for (int o = 16; o > 0; o >>= 1) ss += __shfl_xor_sync(0xffffffffu, ss, o);
    if ((d & 31) == 0) red[d >> 5] = ss;
    __syncthreads();
    float tot = red[0] + red[1] + red[2] + red[3];
    float r   = rsqrtf(tot * (1.0f / HD) + 1e-8f);
    float xn  = v * r * (1.0f + w[d]);
    sm[d] = xn;
    __syncthreads();
    float rot = (d < HD / 2) ? -sm[d + HD / 2] : sm[d - HD / 2];
    p[d] = xn * cosT[(size_t)s * HD + d] + rot * sinT[(size_t)s * HD + d];
}

// ---------------------------------------------------------------------------
// Sliding-window causal GQA attention (flash-style, fp32) — unchanged (verified)
// ---------------------------------------------------------------------------
#define TQ 32
#define TK 64

__global__ __launch_bounds__(256, 1) void attn_kernel(
    const float* __restrict__ Q, const float* __restrict__ K,
    const float* __restrict__ V, float* __restrict__ O,
    const unsigned char* __restrict__ pad, const int* __restrict__ win_ptr)
{
    extern __shared__ float smem_dyn[];
    float* Ks = smem_dyn;                 // [TK][HD]
    float* Vs = smem_dyn + TK * HD;       // [TK][HD]
    __shared__ unsigned char pads[TK];

    const int qt = blockIdx.x;
    const int n  = blockIdx.y;            // kv head
    const int b  = blockIdx.z;
    const int window = win_ptr[0];

    const int t    = threadIdx.x;
    const int r    = t >> 1;              // query row 0..127
    const int half = t & 1;               // which 64-dim half
    const int gi   = r >> 5;              // group index 0..3
    const int qoff = r & 31;
    const int sq   = qt * TQ + qoff;
    const int hq   = n * GQ + gi;

    const unsigned char padq = pad[(size_t)b * SS + sq];

    float4 qv[16];
    {
        const float4* qp = (const float4*)(Q + (((size_t)(b * SS + sq)) * HQ + hq) * HD + half * 64);
        #pragma unroll
        for (int i = 0; i < 16; i++) qv[i] = qp[i];
    }

    float4 o4[16];
    #pragma unroll
    for (int i = 0; i < 16; i++) o4[i] = make_float4(0.f, 0.f, 0.f, 0.f);
    float m = -1e30f;
    float l = 0.0f;

    const float scale = 0.08838834764831845f;   // 128^-0.5

    const int lo = max(0, qt * TQ - window);
    const int hi = qt * TQ + TQ - 1;

    for (int kt0 = lo; kt0 <= hi; kt0 += TK) {
        __syncthreads();
        #pragma unroll
        for (int u = 0; u < 8; u++) {
            int lin = u * 256 + t;
            int j   = lin >> 5;
            int c   = (lin & 31) << 2;
            int kidx = kt0 + j;
            float4 kk4 = make_float4(0.f, 0.f, 0.f, 0.f);
            float4 vv4 = make_float4(0.f, 0.f, 0.f, 0.f);
            if (kidx < SS) {
                size_t off = (((size_t)(b * SS + kidx)) * HKV + n) * HD + c;
                kk4 = *(const float4*)(K + off);
                vv4 = *(const float4*)(V + off);
            }
            *(float4*)&Ks[j * HD + c] = kk4;
            *(float4*)&Vs[j * HD + c] = vv4;
        }
        if (t < TK) {
            int kidx = kt0 + t;
            pads[t] = (kidx < SS) ? pad[(size_t)b * SS + kidx] : (unsigned char)1;
        }
        __syncthreads();

        for (int j = 0; j < TK; j++) {
            const int kidx = kt0 + j;
            float s = 0.0f;
            const float4* kr = (const float4*)&Ks[j * HD + half * 64];
            #pragma unroll
            for (int i = 0; i < 16; i++) {
                float4 kk4 = kr[i];
                s += qv[i].x * kk4.x + qv[i].y * kk4.y + qv[i].z * kk4.z + qv[i].w * kk4.w;
            }
            s += __shfl_xor_sync(0xffffffffu, s, 1);
            s *= scale;

            bool valid = (kidx <= sq) && (sq - kidx <= window) && !pads[j] && !padq;
            if (valid) {
                if (s > m) {
                    float c = __expf(m - s);
                    m = s;
                    l *= c;
                    #pragma unroll
                    for (int i = 0; i < 16; i++) {
                        o4[i].x *= c; o4[i].y *= c; o4[i].z *= c; o4[i].w *= c;
                    }
                }
                float p = __expf(s - m);
                l += p;
                const float4* vr = (const float4*)&Vs[j * HD + half * 64];
                #pragma unroll
                for (int i = 0; i < 16; i++) {
                    float4 vv = vr[i];
                    o4[i].x += p * vv.x; o4[i].y += p * vv.y;
                    o4[i].z += p * vv.z; o4[i].w += p * vv.w;
                }
            }
        }
    }

    float inv = 1.0f / l;
    float4* op = (float4*)(O + (((size_t)(b * SS + sq)) * HQ + hq) * HD + half * 64);
    #pragma unroll
    for (int i = 0; i < 16; i++) {
        float4 v;
        v.x = o4[i].x * inv; v.y = o4[i].y * inv;
        v.z = o4[i].z * inv; v.w = o4[i].w * inv;
        op[i] = v;
    }
}

// ---------------------------------------------------------------------------
// launch
// ---------------------------------------------------------------------------
extern "C" void kernel_launch(void* const* d_in, const int* in_sizes, int n_in,
                              void* d_out, int out_size)
{
    const float* x    = (const float*)d_in[0];
    const float* Wq   = (const float*)d_in[1];
    const float* Wk   = (const float*)d_in[2];
    const float* Wv   = (const float*)d_in[3];
    const float* Wo   = (const float*)d_in[4];
    const float* qnw  = (const float*)d_in[5];
    const float* knw  = (const float*)d_in[6];
    const float* cosT = (const float*)d_in[7];
    const float* sinT = (const float*)d_in[8];
    const unsigned char* pad = (const unsigned char*)d_in[9];
    const int*   win  = (const int*)d_in[10];
    float* out = (float*)d_out;

    float *qbuf, *kbuf, *vbuf, *obuf;
    cudaGetSymbolAddress((void**)&qbuf, g_Q);
    cudaGetSymbolAddress((void**)&kbuf, g_K);
    cudaGetSymbolAddress((void**)&vbuf, g_V);
    cudaGetSymbolAddress((void**)&obuf, g_O);

    const int M = BB * SS;     // 4096

    // Fused QKV projections (tf32 split tensor-core GEMM, one launch)
    gemm_qkv_kernel<<<dim3(24, M / GBM), 512>>>(x, Wq, Wk, Wv, qbuf, kbuf, vbuf);

    // RMSNorm + RoPE
    norm_rope_kernel<<<M * HQ, 128>>>(qbuf, qnw, cosT, sinT, HQ);
    norm_rope_kernel<<<M * HKV, 128>>>(kbuf, knw, cosT, sinT, HKV);

    // attention
    static const size_t attn_smem = (size_t)2 * TK * HD * sizeof(float); // 64 KB
    cudaFuncSetAttribute(attn_kernel, cudaFuncAttributeMaxDynamicSharedMemorySize,
                         (int)attn_smem);
    attn_kernel<<<dim3(SS / TQ, HKV, BB), 256, attn_smem>>>(qbuf, kbuf, vbuf, obuf, pad, win);

    // output projection
    gemm_tf32_kernel<<<dim3(DD / GBN, M / GBM), 512>>>(obuf, Wo, out, M, DD, DD);
}

// round 10
// speedup vs baseline: 1.0927x; 1.0927x over previous
#include <cuda_runtime.h>
#include <cuda_bf16.h>
#include <math.h>

// Problem constants
#define BB   2
#define SS   2048
#define DD   2048
#define HQ   16
#define HKV  4
#define HD   128
#define GQ   (HQ / HKV)          // 4

// ---------------------------------------------------------------------------
// Scratch (device globals; no dynamic allocation allowed)
// ---------------------------------------------------------------------------
__device__ float g_Q[(size_t)BB * SS * HQ * HD];
__device__ float g_K[(size_t)BB * SS * HKV * HD];
__device__ float g_V[(size_t)BB * SS * HKV * HD];
__device__ float g_O[(size_t)BB * SS * HQ * HD];

// ---------------------------------------------------------------------------
// TF32 split GEMM v3 = v1 (verified) + A-staging XOR swizzle + reg prefetch.
// C[M,N] = A[M,K] @ B[K,N], row-major. 3-pass tf32 (hi*hi + hi*lo + lo*hi).
// 128x128 block tile, BK=16, 256 threads (8 warps, 4x2), warp tile 32x64.
// Conversion at staging (once per element); consumer is pure LDS+MMA.
// ---------------------------------------------------------------------------
#define GBM 128
#define GBN 128
#define GBK 16
#define AST 136   // smem row stride

// XOR swizzle for the A tile ([k][m] layout): bank-conflict-free for both
// the scalar STS staging pattern and the fragment LDS pattern.
__device__ __forceinline__ int aswz(int k, int m) {
    return k * AST + (m ^ (((k >> 2) & 3) << 3));
}

__device__ __forceinline__ unsigned f2tf32(float f) {
    unsigned u;
    asm("cvt.rna.tf32.f32 %0, %1;" : "=r"(u) : "f"(f));
    return u;
}

__device__ __forceinline__ void mma_tf32(float* c, const unsigned* a, const unsigned* b) {
    asm volatile(
        "mma.sync.aligned.m16n8k8.row.col.f32.tf32.tf32.f32 "
        "{%0,%1,%2,%3}, {%4,%5,%6,%7}, {%8,%9}, {%0,%1,%2,%3};\n"
        : "+f"(c[0]), "+f"(c[1]), "+f"(c[2]), "+f"(c[3])
        : "r"(a[0]), "r"(a[1]), "r"(a[2]), "r"(a[3]), "r"(b[0]), "r"(b[1]));
}

// Shared device body: computes one 128x128 tile of C = A @ B (256 threads).
__device__ __forceinline__ void gemm_tile_body(
    const float* __restrict__ A, const float* __restrict__ B,
    float* __restrict__ C, int K, int Nout, int block_m, int block_n)
{
    __shared__ float As_hi[GBK * AST];
    __shared__ float As_lo[GBK * AST];
    __shared__ float Bs_hi[GBK * AST];
    __shared__ float Bs_lo[GBK * AST];

    const int t    = threadIdx.x;
    const int lane = t & 31;
    const int wid  = t >> 5;
    const int warp_m = (wid & 3) * 32;
    const int warp_n = (wid >> 2) * 64;

    // global load mappings (v1)
    const int ar = t >> 2;            // A row 0..63 (+64)
    const int ac = (t & 3) << 2;      // A col (k) 0,4,8,12
    const int br = t >> 5;            // B row (k) 0..7 (+8)
    const int bc = (t & 31) << 2;     // B col 0..124

    float acc[2][8][4];
    #pragma unroll
    for (int mt = 0; mt < 2; mt++)
        #pragma unroll
        for (int nt = 0; nt < 8; nt++)
            #pragma unroll
            for (int i = 0; i < 4; i++) acc[mt][nt][i] = 0.0f;

    const int lk = lane & 3;          // frag k sub-index
    const int lg = lane >> 2;         // frag group (0..7)

    const int NT = K / GBK;

    // prologue: prefetch tile 0 into registers
    float4 pa[2], pb[2];
    #pragma unroll
    for (int u = 0; u < 2; u++) {
        pa[u] = *(const float4*)(A + (size_t)(block_m + ar + u * 64) * K + ac);
        pb[u] = *(const float4*)(B + (size_t)(br + u * 8) * Nout + block_n + bc);
    }

    for (int i = 0; i < NT; i++) {
        // --- stage tile i from registers, split hi/lo ---
        #pragma unroll
        for (int u = 0; u < 2; u++) {
            const int r = ar + u * 64;
            const float* f = &pa[u].x;
            #pragma unroll
            for (int j = 0; j < 4; j++) {
                unsigned hi = f2tf32(f[j]);
                float lo = f[j] - __uint_as_float(hi);
                As_hi[aswz(ac + j, r)] = __uint_as_float(hi);
                As_lo[aswz(ac + j, r)] = __uint_as_float(f2tf32(lo));
            }
        }
        #pragma unroll
        for (int u = 0; u < 2; u++) {
            const int r = br + u * 8;
            const float* f = &pb[u].x;
            float4 h4, l4;
            float* hp = &h4.x; float* lp = &l4.x;
            #pragma unroll
            for (int j = 0; j < 4; j++) {
                unsigned hi = f2tf32(f[j]);
                float lo = f[j] - __uint_as_float(hi);
                hp[j] = __uint_as_float(hi);
                lp[j] = __uint_as_float(f2tf32(lo));
            }
            *(float4*)&Bs_hi[r * AST + bc] = h4;
            *(float4*)&Bs_lo[r * AST + bc] = l4;
        }
        __syncthreads();

        // --- prefetch tile i+1 (LDGs overlap with the MMA block below) ---
        if (i + 1 < NT) {
            const int k0 = (i + 1) * GBK;
            #pragma unroll
            for (int u = 0; u < 2; u++) {
                pa[u] = *(const float4*)(A + (size_t)(block_m + ar + u * 64) * K + k0 + ac);
                pb[u] = *(const float4*)(B + (size_t)(k0 + br + u * 8) * Nout + block_n + bc);
            }
        }

        // --- compute tile i (v1 mainloop; A index swizzled) ---
        #pragma unroll
        for (int ks = 0; ks < GBK; ks += 8) {
            unsigned afr[2][4];
            unsigned bfr[8][2];

            const int ka = ks + lk;
            const int kb = ks + lk + 4;

            // A-hi frags
            #pragma unroll
            for (int mt = 0; mt < 2; mt++) {
                int m0 = warp_m + mt * 16 + lg;
                afr[mt][0] = __float_as_uint(As_hi[aswz(ka, m0)]);
                afr[mt][1] = __float_as_uint(As_hi[aswz(ka, m0 + 8)]);
                afr[mt][2] = __float_as_uint(As_hi[aswz(kb, m0)]);
                afr[mt][3] = __float_as_uint(As_hi[aswz(kb, m0 + 8)]);
            }
            // B-lo frags ; mma (Ahi, Blo)
            #pragma unroll
            for (int nt = 0; nt < 8; nt++) {
                int n0 = warp_n + nt * 8 + lg;
                bfr[nt][0] = __float_as_uint(Bs_lo[ka * AST + n0]);
                bfr[nt][1] = __float_as_uint(Bs_lo[kb * AST + n0]);
            }
            #pragma unroll
            for (int nt = 0; nt < 8; nt++)
                #pragma unroll
                for (int mt = 0; mt < 2; mt++)
                    mma_tf32(acc[mt][nt], afr[mt], bfr[nt]);

            // B-hi frags ; mma (Ahi, Bhi)
            #pragma unroll
            for (int nt = 0; nt < 8; nt++) {
                int n0 = warp_n + nt * 8 + lg;
                bfr[nt][0] = __float_as_uint(Bs_hi[ka * AST + n0]);
                bfr[nt][1] = __float_as_uint(Bs_hi[kb * AST + n0]);
            }
            #pragma unroll
            for (int nt = 0; nt < 8; nt++)
                #pragma unroll
                for (int mt = 0; mt < 2; mt++)
                    mma_tf32(acc[mt][nt], afr[mt], bfr[nt]);

            // A-lo frags ; mma (Alo, Bhi)
            #pragma unroll
            for (int mt = 0; mt < 2; mt++) {
                int m0 = warp_m + mt * 16 + lg;
                afr[mt][0] = __float_as_uint(As_lo[aswz(ka, m0)]);
                afr[mt][1] = __float_as_uint(As_lo[aswz(ka, m0 + 8)]);
                afr[mt][2] = __float_as_uint(As_lo[aswz(kb, m0)]);
                afr[mt][3] = __float_as_uint(As_lo[aswz(kb, m0 + 8)]);
            }
            #pragma unroll
            for (int nt = 0; nt < 8; nt++)
                #pragma unroll
                for (int mt = 0; mt < 2; mt++)
                    mma_tf32(acc[mt][nt], afr[mt], bfr[nt]);
        }
        __syncthreads();   // smem reuse fence before next staging
    }

    // epilogue (identical to verified R7 kernel)
    #pragma unroll
    for (int mt = 0; mt < 2; mt++) {
        #pragma unroll
        for (int nt = 0; nt < 8; nt++) {
            int r0 = block_m + warp_m + mt * 16 + lg;
            int c0 = block_n + warp_n + nt * 8 + lk * 2;
            *(float2*)(C + (size_t)r0 * Nout + c0)       = make_float2(acc[mt][nt][0], acc[mt][nt][1]);
            *(float2*)(C + (size_t)(r0 + 8) * Nout + c0) = make_float2(acc[mt][nt][2], acc[mt][nt][3]);
        }
    }
}

// Plain GEMM (used for the output projection)
__global__ __launch_bounds__(256, 2) void gemm_tf32_kernel(
    const float* __restrict__ A, const float* __restrict__ B,
    float* __restrict__ C, int M, int N, int K)
{
    gemm_tile_body(A, B, C, K, N, blockIdx.y * GBM, blockIdx.x * GBN);
}

// Fused QKV projection: one launch, N-tiles routed to (Wq,gQ)/(Wk,gK)/(Wv,gV).
__global__ __launch_bounds__(256, 2) void gemm_qkv_kernel(
    const float* __restrict__ x,
    const float* __restrict__ Wq, const float* __restrict__ Wk,
    const float* __restrict__ Wv,
    float* __restrict__ Qo, float* __restrict__ Ko, float* __restrict__ Vo)
{
    const int nt = blockIdx.x;
    const float* Bp;
    float* Cp;
    int Nout, tile;
    if (nt < 16)      { Bp = Wq; Cp = Qo; Nout = HQ * HD;  tile = nt; }
    else if (nt < 20) { Bp = Wk; Cp = Ko; Nout = HKV * HD; tile = nt - 16; }
    else              { Bp = Wv; Cp = Vo; Nout = HKV * HD; tile = nt - 20; }
    gemm_tile_body(x, Bp, Cp, DD, Nout, blockIdx.y * GBM, tile * GBN);
}

// ---------------------------------------------------------------------------
// Fused RMSNorm + RoPE (in place), one block per (b*S+s, head) row of 128
// ---------------------------------------------------------------------------
__global__ __launch_bounds__(128) void norm_rope_kernel(
    float* __restrict__ X, const float* __restrict__ w,
    const float* __restrict__ cosT, const float* __restrict__ sinT, int H)
{
    __shared__ float sm[HD];
    __shared__ float red[4];

    const int idx = blockIdx.x;
    const int h   = idx % H;
    const int row = idx / H;       // b*S + s
    const int s   = row % SS;
    float* p = X + (size_t)row * (H * HD) + h * HD;

    const int d = threadIdx.x;
    float v  = p[d];
    float ss = v * v;
    #pragma unroll
    for (int o = 16; o > 0; o >>= 1) ss += __shfl_xor_sync(0xffffffffu, ss, o);
    if ((d & 31) == 0) red[d >> 5] = ss;
    __syncthreads();
    float tot = red[0] + red[1] + red[2] + red[3];
    float r   = rsqrtf(tot * (1.0f / HD) + 1e-8f);
    float xn  = v * r * (1.0f + w[d]);
    sm[d] = xn;
    __syncthreads();
    float rot = (d < HD / 2) ? -sm[d + HD / 2] : sm[d - HD / 2];
    p[d] = xn * cosT[(size_t)s * HD + d] + rot * sinT[(size_t)s * HD + d];
}

// ---------------------------------------------------------------------------
// Sliding-window causal GQA attention (flash-style, fp32) — unchanged (verified)
// ---------------------------------------------------------------------------
#define TQ 32
#define TK 64

__global__ __launch_bounds__(256, 1) void attn_kernel(
    const float* __restrict__ Q, const float* __restrict__ K,
    const float* __restrict__ V, float* __restrict__ O,
    const unsigned char* __restrict__ pad, const int* __restrict__ win_ptr)
{
    extern __shared__ float smem_dyn[];
    float* Ks = smem_dyn;                 // [TK][HD]
    float* Vs = smem_dyn + TK * HD;       // [TK][HD]
    __shared__ unsigned char pads[TK];

    const int qt = blockIdx.x;
    const int n  = blockIdx.y;            // kv head
    const int b  = blockIdx.z;
    const int window = win_ptr[0];

    const int t    = threadIdx.x;
    const int r    = t >> 1;              // query row 0..127
    const int half = t & 1;               // which 64-dim half
    const int gi   = r >> 5;              // group index 0..3
    const int qoff = r & 31;
    const int sq   = qt * TQ + qoff;
    const int hq   = n * GQ + gi;

    const unsigned char padq = pad[(size_t)b * SS + sq];

    float4 qv[16];
    {
        const float4* qp = (const float4*)(Q + (((size_t)(b * SS + sq)) * HQ + hq) * HD + half * 64);
        #pragma unroll
        for (int i = 0; i < 16; i++) qv[i] = qp[i];
    }

    float4 o4[16];
    #pragma unroll
    for (int i = 0; i < 16; i++) o4[i] = make_float4(0.f, 0.f, 0.f, 0.f);
    float m = -1e30f;
    float l = 0.0f;

    const float scale = 0.08838834764831845f;   // 128^-0.5

    const int lo = max(0, qt * TQ - window);
    const int hi = qt * TQ + TQ - 1;

    for (int kt0 = lo; kt0 <= hi; kt0 += TK) {
        __syncthreads();
        #pragma unroll
        for (int u = 0; u < 8; u++) {
            int lin = u * 256 + t;
            int j   = lin >> 5;
            int c   = (lin & 31) << 2;
            int kidx = kt0 + j;
            float4 kk4 = make_float4(0.f, 0.f, 0.f, 0.f);
            float4 vv4 = make_float4(0.f, 0.f, 0.f, 0.f);
            if (kidx < SS) {
                size_t off = (((size_t)(b * SS + kidx)) * HKV + n) * HD + c;
                kk4 = *(const float4*)(K + off);
                vv4 = *(const float4*)(V + off);
            }
            *(float4*)&Ks[j * HD + c] = kk4;
            *(float4*)&Vs[j * HD + c] = vv4;
        }
        if (t < TK) {
            int kidx = kt0 + t;
            pads[t] = (kidx < SS) ? pad[(size_t)b * SS + kidx] : (unsigned char)1;
        }
        __syncthreads();

        for (int j = 0; j < TK; j++) {
            const int kidx = kt0 + j;
            float s = 0.0f;
            const float4* kr = (const float4*)&Ks[j * HD + half * 64];
            #pragma unroll
            for (int i = 0; i < 16; i++) {
                float4 kk4 = kr[i];
                s += qv[i].x * kk4.x + qv[i].y * kk4.y + qv[i].z * kk4.z + qv[i].w * kk4.w;
            }
            s += __shfl_xor_sync(0xffffffffu, s, 1);
            s *= scale;

            bool valid = (kidx <= sq) && (sq - kidx <= window) && !pads[j] && !padq;
            if (valid) {
                if (s > m) {
                    float c = __expf(m - s);
                    m = s;
                    l *= c;
                    #pragma unroll
                    for (int i = 0; i < 16; i++) {
                        o4[i].x *= c; o4[i].y *= c; o4[i].z *= c; o4[i].w *= c;
                    }
                }
                float p = __expf(s - m);
                l += p;
                const float4* vr = (const float4*)&Vs[j * HD + half * 64];
                #pragma unroll
                for (int i = 0; i < 16; i++) {
                    float4 vv = vr[i];
                    o4[i].x += p * vv.x; o4[i].y += p * vv.y;
                    o4[i].z += p * vv.z; o4[i].w += p * vv.w;
                }
            }
        }
    }

    float inv = 1.0f / l;
    float4* op = (float4*)(O + (((size_t)(b * SS + sq)) * HQ + hq) * HD + half * 64);
    #pragma unroll
    for (int i = 0; i < 16; i++) {
        float4 v;
        v.x = o4[i].x * inv; v.y = o4[i].y * inv;
        v.z = o4[i].z * inv; v.w = o4[i].w * inv;
        op[i] = v;
    }
}

// ---------------------------------------------------------------------------
// launch
// ---------------------------------------------------------------------------
extern "C" void kernel_launch(void* const* d_in, const int* in_sizes, int n_in,
                              void* d_out, int out_size)
{
    const float* x    = (const float*)d_in[0];
    const float* Wq   = (const float*)d_in[1];
    const float* Wk   = (const float*)d_in[2];
    const float* Wv   = (const float*)d_in[3];
    const float* Wo   = (const float*)d_in[4];
    const float* qnw  = (const float*)d_in[5];
    const float* knw  = (const float*)d_in[6];
    const float* cosT = (const float*)d_in[7];
    const float* sinT = (const float*)d_in[8];
    const unsigned char* pad = (const unsigned char*)d_in[9];
    const int*   win  = (const int*)d_in[10];
    float* out = (float*)d_out;

    float *qbuf, *kbuf, *vbuf, *obuf;
    cudaGetSymbolAddress((void**)&qbuf, g_Q);
    cudaGetSymbolAddress((void**)&kbuf, g_K);
    cudaGetSymbolAddress((void**)&vbuf, g_V);
    cudaGetSymbolAddress((void**)&obuf, g_O);

    const int M = BB * SS;     // 4096

    // Fused QKV projections (tf32 split tensor-core GEMM, one launch)
    gemm_qkv_kernel<<<dim3(24, M / GBM), 256>>>(x, Wq, Wk, Wv, qbuf, kbuf, vbuf);

    // RMSNorm + RoPE
    norm_rope_kernel<<<M * HQ, 128>>>(qbuf, qnw, cosT, sinT, HQ);
    norm_rope_kernel<<<M * HKV, 128>>>(kbuf, knw, cosT, sinT, HKV);

    // attention
    static const size_t attn_smem = (size_t)2 * TK * HD * sizeof(float); // 64 KB
    cudaFuncSetAttribute(attn_kernel, cudaFuncAttributeMaxDynamicSharedMemorySize,
                         (int)attn_smem);
    attn_kernel<<<dim3(SS / TQ, HKV, BB), 256, attn_smem>>>(qbuf, kbuf, vbuf, obuf, pad, win);

    // output projection
    gemm_tf32_kernel<<<dim3(DD / GBN, M / GBM), 256>>>(obuf, Wo, out, M, DD, DD);
}

// round 14
// speedup vs baseline: 1.4202x; 1.2998x over previous
#include <cuda_runtime.h>
#include <cuda_bf16.h>
#include <math.h>

// Problem constants
#define BB   2
#define SS   2048
#define DD   2048
#define HQ   16
#define HKV  4
#define HD   128
#define GQ   (HQ / HKV)          // 4

// ---------------------------------------------------------------------------
// Scratch (device globals; no dynamic allocation allowed)
// ---------------------------------------------------------------------------
__device__ float g_Q[(size_t)BB * SS * HQ * HD];
__device__ float g_K[(size_t)BB * SS * HKV * HD];
__device__ float g_V[(size_t)BB * SS * HKV * HD];
__device__ float g_O[(size_t)BB * SS * HQ * HD];

// ---------------------------------------------------------------------------
// BF16 split GEMM v4: 3-pass bf16 split (hi*hi + hi*lo + lo*hi) via
// mma.sync.m16n8k16 (4096 FLOP/instr = 2x tf32 m16n8k8).
// C[M,N] = A[M,K] @ B[K,N], row-major.
// 128x128 block tile, BK=16 (= one full MMA K), 256 threads (8 warps, 4x2),
// warp tile 32x64. Conversion+packing at staging; consumer is pure LDS+MMA.
// Register prefetch of the next tile overlaps LDG with MMA.
// ---------------------------------------------------------------------------
#define GBM 128
#define GBN 128
#define GBK 16
#define KP  8      // k-pairs per tile (GBK/2)
#define ASTR 12    // A smem stride (words) per m-row: bank 12*lg+lk all-distinct
#define BSTR 136   // B smem stride (words) per kpair-row: bank 8*lk+lg distinct

// pack two fp32 -> bf16x2 word (lower k in low 16 bits)
__device__ __forceinline__ unsigned pack_hi(float f0, float f1) {
    __nv_bfloat162 p;
    p.x = __float2bfloat16_rn(f0);
    p.y = __float2bfloat16_rn(f1);
    return *reinterpret_cast<unsigned*>(&p);
}
__device__ __forceinline__ unsigned pack_lo(float f0, float f1) {
    __nv_bfloat162 p;
    __nv_bfloat16 h0 = __float2bfloat16_rn(f0);
    __nv_bfloat16 h1 = __float2bfloat16_rn(f1);
    p.x = __float2bfloat16_rn(f0 - __bfloat162float(h0));
    p.y = __float2bfloat16_rn(f1 - __bfloat162float(h1));
    return *reinterpret_cast<unsigned*>(&p);
}

__device__ __forceinline__ void mma_bf16(float* c, const unsigned* a, const unsigned* b) {
    asm volatile(
        "mma.sync.aligned.m16n8k16.row.col.f32.bf16.bf16.f32 "
        "{%0,%1,%2,%3}, {%4,%5,%6,%7}, {%8,%9}, {%0,%1,%2,%3};\n"
        : "+f"(c[0]), "+f"(c[1]), "+f"(c[2]), "+f"(c[3])
        : "r"(a[0]), "r"(a[1]), "r"(a[2]), "r"(a[3]), "r"(b[0]), "r"(b[1]));
}

// Shared device body: computes one 128x128 tile of C = A @ B (256 threads).
__device__ __forceinline__ void gemm_tile_body(
    const float* __restrict__ A, const float* __restrict__ B,
    float* __restrict__ C, int K, int Nout, int block_m, int block_n)
{
    // bf16x2 words
    __shared__ unsigned As_hi[GBM * ASTR];   // [m][kpair]
    __shared__ unsigned As_lo[GBM * ASTR];
    __shared__ unsigned Bs_hi[KP * BSTR];    // [kpair][n]
    __shared__ unsigned Bs_lo[KP * BSTR];

    const int t    = threadIdx.x;
    const int lane = t & 31;
    const int wid  = t >> 5;
    const int warp_m = (wid & 3) * 32;
    const int warp_n = (wid >> 2) * 64;

    // global load mappings
    const int ar = t >> 2;            // A row 0..63 (+64)
    const int ac = (t & 3) << 2;      // A col (k) 0,4,8,12
    const int bkp = t >> 5;           // B kpair 0..7
    const int bc  = (t & 31) << 2;    // B col 0..124

    float acc[2][8][4];
    #pragma unroll
    for (int mt = 0; mt < 2; mt++)
        #pragma unroll
        for (int nt = 0; nt < 8; nt++)
            #pragma unroll
            for (int i = 0; i < 4; i++) acc[mt][nt][i] = 0.0f;

    const int lk = lane & 3;          // frag kpair sub-index
    const int lg = lane >> 2;         // frag group (0..7)

    const int NT = K / GBK;

    // prologue: prefetch tile 0 into registers
    float4 pa[2], pb0, pb1;
    #pragma unroll
    for (int u = 0; u < 2; u++)
        pa[u] = *(const float4*)(A + (size_t)(block_m + ar + u * 64) * K + ac);
    pb0 = *(const float4*)(B + (size_t)(2 * bkp)     * Nout + block_n + bc);
    pb1 = *(const float4*)(B + (size_t)(2 * bkp + 1) * Nout + block_n + bc);

    for (int i = 0; i < NT; i++) {
        // --- stage tile i from registers, split hi/lo, pack bf16x2 ---
        #pragma unroll
        for (int u = 0; u < 2; u++) {
            const int r = ar + u * 64;
            const float* f = &pa[u].x;
            const int kp0 = ac >> 1;                 // 0,2,4,6
            As_hi[r * ASTR + kp0]     = pack_hi(f[0], f[1]);
            As_hi[r * ASTR + kp0 + 1] = pack_hi(f[2], f[3]);
            As_lo[r * ASTR + kp0]     = pack_lo(f[0], f[1]);
            As_lo[r * ASTR + kp0 + 1] = pack_lo(f[2], f[3]);
        }
        {
            const float* f0 = &pb0.x;
            const float* f1 = &pb1.x;
            unsigned h[4], l[4];
            #pragma unroll
            for (int j = 0; j < 4; j++) {
                h[j] = pack_hi(f0[j], f1[j]);        // (k=2kp, k=2kp+1) for col bc+j
                l[j] = pack_lo(f0[j], f1[j]);
            }
            *(uint4*)&Bs_hi[bkp * BSTR + bc] = make_uint4(h[0], h[1], h[2], h[3]);
            *(uint4*)&Bs_lo[bkp * BSTR + bc] = make_uint4(l[0], l[1], l[2], l[3]);
        }
        __syncthreads();

        // --- prefetch tile i+1 (LDGs overlap with the MMA block below) ---
        if (i + 1 < NT) {
            const int k0 = (i + 1) * GBK;
            #pragma unroll
            for (int u = 0; u < 2; u++)
                pa[u] = *(const float4*)(A + (size_t)(block_m + ar + u * 64) * K + k0 + ac);
            pb0 = *(const float4*)(B + (size_t)(k0 + 2 * bkp)     * Nout + block_n + bc);
            pb1 = *(const float4*)(B + (size_t)(k0 + 2 * bkp + 1) * Nout + block_n + bc);
        }

        // --- compute tile i: one m16n8k16 fragment set covers GBK=16 ---
        {
            unsigned afr[2][4];
            unsigned bfr[8][2];

            // A-hi frags
            #pragma unroll
            for (int mt = 0; mt < 2; mt++) {
                const int m0 = warp_m + mt * 16 + lg;
                afr[mt][0] = As_hi[m0 * ASTR + lk];            // (m0,   k=2lk..)
                afr[mt][1] = As_hi[(m0 + 8) * ASTR + lk];      // (m0+8, k=2lk..)
                afr[mt][2] = As_hi[m0 * ASTR + lk + 4];        // (m0,   k=8+2lk..)
                afr[mt][3] = As_hi[(m0 + 8) * ASTR + lk + 4];  // (m0+8, k=8+2lk..)
            }
            // B-lo frags ; pass 1: Ahi * Blo
            #pragma unroll
            for (int nt = 0; nt < 8; nt++) {
                const int n0 = warp_n + nt * 8 + lg;
                bfr[nt][0] = Bs_lo[lk * BSTR + n0];
                bfr[nt][1] = Bs_lo[(lk + 4) * BSTR + n0];
            }
            #pragma unroll
            for (int nt = 0; nt < 8; nt++)
                #pragma unroll
                for (int mt = 0; mt < 2; mt++)
                    mma_bf16(acc[mt][nt], afr[mt], bfr[nt]);

            // B-hi frags ; pass 2: Ahi * Bhi
            #pragma unroll
            for (int nt = 0; nt < 8; nt++) {
                const int n0 = warp_n + nt * 8 + lg;
                bfr[nt][0] = Bs_hi[lk * BSTR + n0];
                bfr[nt][1] = Bs_hi[(lk + 4) * BSTR + n0];
            }
            #pragma unroll
            for (int nt = 0; nt < 8; nt++)
                #pragma unroll
                for (int mt = 0; mt < 2; mt++)
                    mma_bf16(acc[mt][nt], afr[mt], bfr[nt]);

            // A-lo frags ; pass 3: Alo * Bhi
            #pragma unroll
            for (int mt = 0; mt < 2; mt++) {
                const int m0 = warp_m + mt * 16 + lg;
                afr[mt][0] = As_lo[m0 * ASTR + lk];
                afr[mt][1] = As_lo[(m0 + 8) * ASTR + lk];
                afr[mt][2] = As_lo[m0 * ASTR + lk + 4];
                afr[mt][3] = As_lo[(m0 + 8) * ASTR + lk + 4];
            }
            #pragma unroll
            for (int nt = 0; nt < 8; nt++)
                #pragma unroll
                for (int mt = 0; mt < 2; mt++)
                    mma_bf16(acc[mt][nt], afr[mt], bfr[nt]);
        }
        __syncthreads();   // smem reuse fence before next staging
    }

    // epilogue (fragment layout identical to verified kernel)
    #pragma unroll
    for (int mt = 0; mt < 2; mt++) {
        #pragma unroll
        for (int nt = 0; nt < 8; nt++) {
            int r0 = block_m + warp_m + mt * 16 + lg;
            int c0 = block_n + warp_n + nt * 8 + lk * 2;
            *(float2*)(C + (size_t)r0 * Nout + c0)       = make_float2(acc[mt][nt][0], acc[mt][nt][1]);
            *(float2*)(C + (size_t)(r0 + 8) * Nout + c0) = make_float2(acc[mt][nt][2], acc[mt][nt][3]);
        }
    }
}

// Plain GEMM (used for the output projection)
__global__ __launch_bounds__(256, 2) void gemm_bf16_kernel(
    const float* __restrict__ A, const float* __restrict__ B,
    float* __restrict__ C, int M, int N, int K)
{
    gemm_tile_body(A, B, C, K, N, blockIdx.y * GBM, blockIdx.x * GBN);
}

// Fused QKV projection: one launch, N-tiles routed to (Wq,gQ)/(Wk,gK)/(Wv,gV).
__global__ __launch_bounds__(256, 2) void gemm_qkv_kernel(
    const float* __restrict__ x,
    const float* __restrict__ Wq, const float* __restrict__ Wk,
    const float* __restrict__ Wv,
    float* __restrict__ Qo, float* __restrict__ Ko, float* __restrict__ Vo)
{
    const int nt = blockIdx.x;
    const float* Bp;
    float* Cp;
    int Nout, tile;
    if (nt < 16)      { Bp = Wq; Cp = Qo; Nout = HQ * HD;  tile = nt; }
    else if (nt < 20) { Bp = Wk; Cp = Ko; Nout = HKV * HD; tile = nt - 16; }
    else              { Bp = Wv; Cp = Vo; Nout = HKV * HD; tile = nt - 20; }
    gemm_tile_body(x, Bp, Cp, DD, Nout, blockIdx.y * GBM, tile * GBN);
}

// ---------------------------------------------------------------------------
// Fused RMSNorm + RoPE (in place), one block per (b*S+s, head) row of 128
// ---------------------------------------------------------------------------
__global__ __launch_bounds__(128) void norm_rope_kernel(
    float* __restrict__ X, const float* __restrict__ w,
    const float* __restrict__ cosT, const float* __restrict__ sinT, int H)
{
    __shared__ float sm[HD];
    __shared__ float red[4];

    const int idx = blockIdx.x;
    const int h   = idx % H;
    const int row = idx / H;       // b*S + s
    const int s   = row % SS;
    float* p = X + (size_t)row * (H * HD) + h * HD;

    const int d = threadIdx.x;
    float v  = p[d];
    float ss = v * v;
    #pragma unroll
    for (int o = 16; o > 0; o >>= 1) ss += __shfl_xor_sync(0xffffffffu, ss, o);
    if ((d & 31) == 0) red[d >> 5] = ss;
    __syncthreads();
    float tot = red[0] + red[1] + red[2] + red[3];
    float r   = rsqrtf(tot * (1.0f / HD) + 1e-8f);
    float xn  = v * r * (1.0f + w[d]);
    sm[d] = xn;
    __syncthreads();
    float rot = (d < HD / 2) ? -sm[d + HD / 2] : sm[d - HD / 2];
    p[d] = xn * cosT[(size_t)s * HD + d] + rot * sinT[(size_t)s * HD + d];
}

// ---------------------------------------------------------------------------
// Sliding-window causal GQA attention (flash-style, fp32) — unchanged (verified)
// ---------------------------------------------------------------------------
#define TQ 32
#define TK 64

__global__ __launch_bounds__(256, 1) void attn_kernel(
    const float* __restrict__ Q, const float* __restrict__ K,
    const float* __restrict__ V, float* __restrict__ O,
    const unsigned char* __restrict__ pad, const int* __restrict__ win_ptr)
{
    extern __shared__ float smem_dyn[];
    float* Ks = smem_dyn;                 // [TK][HD]
    float* Vs = smem_dyn + TK * HD;       // [TK][HD]
    __shared__ unsigned char pads[TK];

    const int qt = blockIdx.x;
    const int n  = blockIdx.y;            // kv head
    const int b  = blockIdx.z;
    const int window = win_ptr[0];

    const int t    = threadIdx.x;
    const int r    = t >> 1;              // query row 0..127
    const int half = t & 1;               // which 64-dim half
    const int gi   = r >> 5;              // group index 0..3
    const int qoff = r & 31;
    const int sq   = qt * TQ + qoff;
    const int hq   = n * GQ + gi;

    const unsigned char padq = pad[(size_t)b * SS + sq];

    float4 qv[16];
    {
        const float4* qp = (const float4*)(Q + (((size_t)(b * SS + sq)) * HQ + hq) * HD + half * 64);
        #pragma unroll
        for (int i = 0; i < 16; i++) qv[i] = qp[i];
    }

    float4 o4[16];
    #pragma unroll
    for (int i = 0; i < 16; i++) o4[i] = make_float4(0.f, 0.f, 0.f, 0.f);
    float m = -1e30f;
    float l = 0.0f;

    const float scale = 0.08838834764831845f;   // 128^-0.5

    const int lo = max(0, qt * TQ - window);
    const int hi = qt * TQ + TQ - 1;

    for (int kt0 = lo; kt0 <= hi; kt0 += TK) {
        __syncthreads();
        #pragma unroll
        for (int u = 0; u < 8; u++) {
            int lin = u * 256 + t;
            int j   = lin >> 5;
            int c   = (lin & 31) << 2;
            int kidx = kt0 + j;
            float4 kk4 = make_float4(0.f, 0.f, 0.f, 0.f);
            float4 vv4 = make_float4(0.f, 0.f, 0.f, 0.f);
            if (kidx < SS) {
                size_t off = (((size_t)(b * SS + kidx)) * HKV + n) * HD + c;
                kk4 = *(const float4*)(K + off);
                vv4 = *(const float4*)(V + off);
            }
            *(float4*)&Ks[j * HD + c] = kk4;
            *(float4*)&Vs[j * HD + c] = vv4;
        }
        if (t < TK) {
            int kidx = kt0 + t;
            pads[t] = (kidx < SS) ? pad[(size_t)b * SS + kidx] : (unsigned char)1;
        }
        __syncthreads();

        for (int j = 0; j < TK; j++) {
            const int kidx = kt0 + j;
            float s = 0.0f;
            const float4* kr = (const float4*)&Ks[j * HD + half * 64];
            #pragma unroll
            for (int i = 0; i < 16; i++) {
                float4 kk4 = kr[i];
                s += qv[i].x * kk4.x + qv[i].y * kk4.y + qv[i].z * kk4.z + qv[i].w * kk4.w;
            }
            s += __shfl_xor_sync(0xffffffffu, s, 1);
            s *= scale;

            bool valid = (kidx <= sq) && (sq - kidx <= window) && !pads[j] && !padq;
            if (valid) {
                if (s > m) {
                    float c = __expf(m - s);
                    m = s;
                    l *= c;
                    #pragma unroll
                    for (int i = 0; i < 16; i++) {
                        o4[i].x *= c; o4[i].y *= c; o4[i].z *= c; o4[i].w *= c;
                    }
                }
                float p = __expf(s - m);
                l += p;
                const float4* vr = (const float4*)&Vs[j * HD + half * 64];
                #pragma unroll
                for (int i = 0; i < 16; i++) {
                    float4 vv = vr[i];
                    o4[i].x += p * vv.x; o4[i].y += p * vv.y;
                    o4[i].z += p * vv.z; o4[i].w += p * vv.w;
                }
            }
        }
    }

    float inv = 1.0f / l;
    float4* op = (float4*)(O + (((size_t)(b * SS + sq)) * HQ + hq) * HD + half * 64);
    #pragma unroll
    for (int i = 0; i < 16; i++) {
        float4 v;
        v.x = o4[i].x * inv; v.y = o4[i].y * inv;
        v.z = o4[i].z * inv; v.w = o4[i].w * inv;
        op[i] = v;
    }
}

// ---------------------------------------------------------------------------
// launch
// ---------------------------------------------------------------------------
extern "C" void kernel_launch(void* const* d_in, const int* in_sizes, int n_in,
                              void* d_out, int out_size)
{
    const float* x    = (const float*)d_in[0];
    const float* Wq   = (const float*)d_in[1];
    const float* Wk   = (const float*)d_in[2];
    const float* Wv   = (const float*)d_in[3];
    const float* Wo   = (const float*)d_in[4];
    const float* qnw  = (const float*)d_in[5];
    const float* knw  = (const float*)d_in[6];
    const float* cosT = (const float*)d_in[7];
    const float* sinT = (const float*)d_in[8];
    const unsigned char* pad = (const unsigned char*)d_in[9];
    const int*   win  = (const int*)d_in[10];
    float* out = (float*)d_out;

    float *qbuf, *kbuf, *vbuf, *obuf;
    cudaGetSymbolAddress((void**)&qbuf, g_Q);
    cudaGetSymbolAddress((void**)&kbuf, g_K);
    cudaGetSymbolAddress((void**)&vbuf, g_V);
    cudaGetSymbolAddress((void**)&obuf, g_O);

    const int M = BB * SS;     // 4096

    // Fused QKV projections (bf16 split tensor-core GEMM, one launch)
    gemm_qkv_kernel<<<dim3(24, M / GBM), 256>>>(x, Wq, Wk, Wv, qbuf, kbuf, vbuf);

    // RMSNorm + RoPE
    norm_rope_kernel<<<M * HQ, 128>>>(qbuf, qnw, cosT, sinT, HQ);
    norm_rope_kernel<<<M * HKV, 128>>>(kbuf, knw, cosT, sinT, HKV);

    // attention
    static const size_t attn_smem = (size_t)2 * TK * HD * sizeof(float); // 64 KB
    cudaFuncSetAttribute(attn_kernel, cudaFuncAttributeMaxDynamicSharedMemorySize,
                         (int)attn_smem);
    attn_kernel<<<dim3(SS / TQ, HKV, BB), 256, attn_smem>>>(qbuf, kbuf, vbuf, obuf, pad, win);

    // output projection
    gemm_bf16_kernel<<<dim3(DD / GBN, M / GBM), 256>>>(obuf, Wo, out, M, DD, DD);
}